// round 5
// baseline (speedup 1.0000x reference)
#include <cuda_runtime.h>
#include <math.h>
#include <stdint.h>

// ---------------------------------------------------------------------------
// BertAdapterCapsuleMask fused pipeline.
// Round 5: R4 design with a pure-kernel-launch path (no host API calls in
// kernel_launch). tf32 mma GEMMs + ldmatrix fragments; B pre-transposed.
// Shapes: B=256 S=128 H=768 A=512 N=10 C=3 K=3.  M = 32768.
// ---------------------------------------------------------------------------

#define MROWS 32768
#define HDIM  768
#define ADIM  512
#define NTASK 10
#define CCAP  3
#define KCAP  3

// Scratch (static device globals; no allocations anywhere)
__device__ float g_sem[(size_t)MROWS * 30];
__device__ float g_vote[(size_t)KCAP * MROWS * CCAP];
__device__ float g_h2[(size_t)MROWS * HDIM];
__device__ float g_a[(size_t)MROWS * ADIM];
__device__ float g_wt1[(size_t)ADIM * HDIM];   // fc1_w^T  [N=512][K=768]
__device__ float g_wt2[(size_t)HDIM * ADIM];   // fc2_w^T  [N=768][K=512]
__device__ float g_gfc1[ADIM];
__device__ float g_gfc2[HDIM];
__device__ float g_glarger[HDIM];

// ---- packed fp32x2 helpers (used by k1 skinny GEMM)
__device__ __forceinline__ unsigned long long pk2(float x) {
    unsigned long long r;
    asm("mov.b64 %0, {%1, %1};" : "=l"(r) : "f"(x));
    return r;
}
__device__ __forceinline__ void ffma2(unsigned long long& d, unsigned long long a,
                                      unsigned long long b) {
    asm("fma.rn.f32x2 %0, %1, %2, %0;" : "+l"(d) : "l"(a), "l"(b));
}
__device__ __forceinline__ void unpk2(unsigned long long v, float& lo, float& hi) {
    asm("mov.b64 {%0, %1}, %2;" : "=f"(lo), "=f"(hi) : "l"(v));
}

__device__ __forceinline__ float gelu_exact(float v) {
    return 0.5f * v * (1.0f + erff(v * 0.7071067811865476f));
}
__device__ __forceinline__ float sigmoid_(float z) {
    return 1.0f / (1.0f + expf(-z));
}

// ---- cp.async helpers
__device__ __forceinline__ void cp_async16(uint32_t smem_dst, const void* gsrc) {
    asm volatile("cp.async.cg.shared.global [%0], [%1], 16;" ::"r"(smem_dst), "l"(gsrc));
}
__device__ __forceinline__ void cp_commit() {
    asm volatile("cp.async.commit_group;");
}
template <int N>
__device__ __forceinline__ void cp_wait() {
    asm volatile("cp.async.wait_group %0;" ::"n"(N));
}

// ---- ldmatrix x4 (b16 view; loads tf32/f32 fragments, 4 regs)
__device__ __forceinline__ void ldsm4(uint32_t& r0, uint32_t& r1, uint32_t& r2,
                                      uint32_t& r3, uint32_t addr) {
    asm volatile("ldmatrix.sync.aligned.m8n8.x4.shared.b16 {%0,%1,%2,%3}, [%4];"
                 : "=r"(r0), "=r"(r1), "=r"(r2), "=r"(r3)
                 : "r"(addr));
}

// ---- tf32 mma  (m16n8k8, row.col)
__device__ __forceinline__ void mma_tf32(float4& d, const uint32_t* a, const uint32_t* b) {
    asm volatile(
        "mma.sync.aligned.m16n8k8.row.col.f32.tf32.tf32.f32 "
        "{%0,%1,%2,%3}, {%4,%5,%6,%7}, {%8,%9}, {%0,%1,%2,%3};"
        : "+f"(d.x), "+f"(d.y), "+f"(d.z), "+f"(d.w)
        : "r"(a[0]), "r"(a[1]), "r"(a[2]), "r"(a[3]), "r"(b[0]), "r"(b[1]));
}

// ---------------------------------------------------------------------------
// K0: HAT gates.  g = sigmoid(s * e[t])
// ---------------------------------------------------------------------------
__global__ void k0_gates(const float* __restrict__ efc1, const float* __restrict__ efc2,
                         const float* __restrict__ elarger,
                         const int* __restrict__ tp, const int* __restrict__ sp) {
    int t = *tp;
    float s = (float)(*sp);
    int h = threadIdx.x;  // 768 threads
    g_glarger[h] = sigmoid_(s * elarger[t * HDIM + h]);
    g_gfc2[h]    = sigmoid_(s * efc2[t * HDIM + h]);
    if (h < ADIM) g_gfc1[h] = sigmoid_(s * efc1[t * ADIM + h]);
}

// ---------------------------------------------------------------------------
// KT: weight transpose  W[K][N] -> Wt[N][K]  into device-global scratch
// (WHICH selects the destination; no host pointer queries needed).
// ---------------------------------------------------------------------------
template <int WHICH>
__global__ void kT(const float* __restrict__ W, int K, int N) {
    float* Wt = (WHICH == 1) ? g_wt1 : g_wt2;
    __shared__ float t[32][33];
    int k0 = blockIdx.x * 32, n0 = blockIdx.y * 32;
    int tx = threadIdx.x, ty = threadIdx.y;  // block (32, 8)
#pragma unroll
    for (int p = 0; p < 32; p += 8) t[ty + p][tx] = W[(size_t)(k0 + ty + p) * N + n0 + tx];
    __syncthreads();
#pragma unroll
    for (int p = 0; p < 32; p += 8)
        Wt[(size_t)(n0 + ty + p) * K + k0 + tx] = t[tx][ty + p];
}

// ---------------------------------------------------------------------------
// K1: semantic-capsule skinny GEMM (f32x2 SIMT) — measured-passing, unchanged.
// ---------------------------------------------------------------------------
__global__ __launch_bounds__(128) void k1_sem(const float* __restrict__ x,
                                              const float* __restrict__ semw,
                                              const float* __restrict__ semb) {
    __shared__ float Xs[128][65];
    __shared__ float Ws[64][32];
    __shared__ float bs[32];

    int tid = threadIdx.x;
    int m0 = blockIdx.x * 128;

    if (tid < 30) {
        int c = tid / 10, n = tid % 10;
        bs[tid] = semb[n * 3 + c];
    }

    unsigned long long acc[15];
#pragma unroll
    for (int j = 0; j < 15; j++) acc[j] = 0ull;

    for (int k0 = 0; k0 < HDIM; k0 += 64) {
#pragma unroll
        for (int p = 0; p < 16; p++) {
            int e = p * 128 + tid;
            int r = e >> 4, c4 = e & 15;
            float4 v = *(const float4*)(x + (size_t)(m0 + r) * HDIM + k0 + c4 * 4);
            Xs[r][c4 * 4 + 0] = v.x;
            Xs[r][c4 * 4 + 1] = v.y;
            Xs[r][c4 * 4 + 2] = v.z;
            Xs[r][c4 * 4 + 3] = v.w;
        }
#pragma unroll
        for (int p = 0; p < 15; p++) {
            int e = p * 128 + tid;
            int kk = e / 30, o = e % 30;
            int c = o / 10, n = o % 10;
            Ws[kk][o] = semw[n * HDIM * 3 + (k0 + kk) * 3 + c];
        }
        __syncthreads();

#pragma unroll 4
        for (int kk = 0; kk < 64; kk++) {
            unsigned long long x2 = pk2(Xs[tid][kk]);
#pragma unroll
            for (int j = 0; j < 15; j++) {
                unsigned long long w2 = *(const unsigned long long*)&Ws[kk][2 * j];
                ffma2(acc[j], x2, w2);
            }
        }
        __syncthreads();
    }

    int m = m0 + tid;
#pragma unroll
    for (int j = 0; j < 15; j++) {
        float lo, hi;
        unpk2(acc[j], lo, hi);
        g_sem[(size_t)m * 30 + 2 * j]     = lo + bs[2 * j];
        g_sem[(size_t)m * 30 + 2 * j + 1] = hi + bs[2 * j + 1];
    }
}

// ---------------------------------------------------------------------------
// K2: squash + dynamic routing — measured-passing, unchanged.
// ---------------------------------------------------------------------------
__global__ __launch_bounds__(256) void k2_route(const float* __restrict__ routew,
                                                const int* __restrict__ tp) {
    __shared__ float rw[KCAP * NTASK * CCAP * CCAP];
    int tid = threadIdx.x;
    if (tid < 270) rw[tid] = routew[tid];
    __syncthreads();

    int t = *tp;
    int m = blockIdx.x * 256 + tid;

    float v[30];
    const float* srow = &g_sem[(size_t)m * 30];
#pragma unroll
    for (int i = 0; i < 30; i++) v[i] = srow[i];

#pragma unroll
    for (int c = 0; c < 3; c++) {
        float sn = 1e-16f;
#pragma unroll
        for (int n = 0; n < 10; n++) { float q = v[c * 10 + n]; sn += q * q; }
        float sc = sqrtf(sn) / (1.0f + sn);
#pragma unroll
        for (int n = 0; n < 10; n++) v[c * 10 + n] *= sc;
    }

#pragma unroll
    for (int k = 0; k < 3; k++) {
        float pr[10][3];
#pragma unroll
        for (int n = 0; n < 10; n++) {
            float u0 = v[n * 3 + 0], u1 = v[n * 3 + 1], u2 = v[n * 3 + 2];
#pragma unroll
            for (int d = 0; d < 3; d++) {
                int b = ((k * 10 + n) * 3) * 3 + d;
                pr[n][d] = u0 * rw[b] + u1 * rw[b + 3] + u2 * rw[b + 6];
            }
        }
        float lg[10];
#pragma unroll
        for (int n = 0; n < 10; n++) lg[n] = 0.0f;

        float vote0 = 0.f, vote1 = 0.f, vote2 = 0.f;
#pragma unroll
        for (int it = 0; it < 3; it++) {
            float mx = -3.4e38f;
#pragma unroll
            for (int n = 0; n < 10; n++) {
                lg[n] = (n <= t) ? lg[n] : -10000.0f;
                mx = fmaxf(mx, lg[n]);
            }
            float e[10], ssum = 0.f;
#pragma unroll
            for (int n = 0; n < 10; n++) { e[n] = expf(lg[n] - mx); ssum += e[n]; }
            float inv = 1.0f / ssum;
            vote0 = vote1 = vote2 = 0.f;
#pragma unroll
            for (int n = 0; n < 10; n++) {
                float p = e[n] * inv;
                vote0 += p * pr[n][0];
                vote1 += p * pr[n][1];
                vote2 += p * pr[n][2];
            }
            if (it < 2) {
                float sn = vote0 * vote0 + vote1 * vote1 + vote2 * vote2 + 1e-16f;
                float sc = sqrtf(sn) / (1.0f + sn);
                float o0 = vote0 * sc, o1 = vote1 * sc, o2 = vote2 * sc;
#pragma unroll
                for (int n = 0; n < 10; n++)
                    lg[n] += pr[n][0] * o0 + pr[n][1] * o1 + pr[n][2] * o2;
            }
        }
        size_t base = ((size_t)k * MROWS + m) * 3;
        g_vote[base + 0] = vote0;
        g_vote[base + 1] = vote1;
        g_vote[base + 2] = vote2;
    }
}

// ---------------------------------------------------------------------------
// K3: h2 = x + glarger * (vote9 @ larger_w + larger_b)
// 32 rows/block; lw column cached in registers (reused over 32 rows),
// vote block in smem (broadcast reads).
// ---------------------------------------------------------------------------
__global__ __launch_bounds__(256) void k3_h2(const float* __restrict__ x,
                                             const float* __restrict__ lw,
                                             const float* __restrict__ lb) {
    __shared__ float v9s[32 * 9];
    int m0 = blockIdx.x * 32;
    int tid = threadIdx.x;
    for (int i = tid; i < 288; i += 256) v9s[i] = g_vote[(size_t)m0 * 9 + i];
    __syncthreads();

#pragma unroll
    for (int p = 0; p < 3; p++) {
        int h = tid + p * 256;
        float lwr[9];
#pragma unroll
        for (int j = 0; j < 9; j++) lwr[j] = lw[j * HDIM + h];
        float gl = g_glarger[h];
        float bb = lb[h];
#pragma unroll 4
        for (int r = 0; r < 32; r++) {
            float acc = bb;
#pragma unroll
            for (int j = 0; j < 9; j++) acc += lwr[j] * v9s[r * 9 + j];
            size_t idx = (size_t)(m0 + r) * HDIM + h;
            g_h2[idx] = x[idx] + gl * acc;
        }
    }
}

// ---------------------------------------------------------------------------
// Adapter GEMMs: mma.sync m16n8k8 tf32, ldmatrix fragment loads.
// BM=128 BN=128 BK=16, 256 threads = 8 warps (2 M x 4 N), warp tile 64x32.
// A smem [128][20] f32 (row-major m,k); B smem [128][20] f32 (n-major from Wt).
// Both fragments via ldmatrix.x4.b16 on the b16 view of f32 tiles.
// 2-stage cp.async double buffering; smem = 40.96 KB (< 48 KB, no opt-in).
// MODE 1: a   = gelu(h2 @ fc1_w + b) * gfc1
// MODE 2: out = x + gelu(a @ fc2_w + b) * gfc2
// ---------------------------------------------------------------------------
#define TSTRIDE 20                   // 16 + 4 pad
#define TILESZ  (128 * TSTRIDE)      // 2560 floats per stage (A or B)
#define GEMM_SMEM_BYTES (4 * TILESZ * 4)   // 40960 B

template <int KDIM, int NDIM, int MODE>
__global__ __launch_bounds__(256, 2) void gemm_mma(const float* __restrict__ bias,
                                                   const float* __restrict__ xin,
                                                   float* __restrict__ outp) {
    extern __shared__ float smem[];
    // layout: [A0][B0][A1][B1]
    const float* A    = (MODE == 1) ? g_h2 : g_a;
    const float* Wt   = (MODE == 1) ? g_wt1 : g_wt2;
    const float* gate = (MODE == 1) ? g_gfc1 : g_gfc2;
    float* C          = (MODE == 1) ? g_a : outp;

    const int tid = threadIdx.x;
    const int lane = tid & 31;
    const int wid = tid >> 5;
    const int warp_m = wid >> 2;   // 0..1
    const int warp_n = wid & 3;    // 0..3
    const int g = lane >> 2;       // 0..7
    const int tg = lane & 3;       // 0..3

    const int n0 = blockIdx.x * 128;
    const int m0 = blockIdx.y * 128;

    // staging: tile 128x16 f32 = 512 float4, 2 per thread (rows r, r+64)
    const int sr = tid >> 2;       // 0..63
    const int scq = tid & 3;       // float4 col within 16-wide k

    uint32_t sbase = (uint32_t)__cvta_generic_to_shared(smem);

    // ldmatrix per-lane addresses (byte offsets within a tile)
    const int a_row = warp_m * 64 + (lane & 15);
    const int a_k4 = (lane >> 4) * 4;
    const uint32_t aoff = (uint32_t)(a_row * TSTRIDE + a_k4) * 4;
    const int b_row = warp_n * 32 + (lane & 7) + ((lane >> 4) << 3);
    const int b_k4 = ((lane >> 3) & 1) * 4;
    const uint32_t boff = (uint32_t)(b_row * TSTRIDE + b_k4) * 4;

    float4 acc[4][4];
#pragma unroll
    for (int i = 0; i < 4; i++)
#pragma unroll
        for (int j = 0; j < 4; j++) acc[i][j] = make_float4(0.f, 0.f, 0.f, 0.f);

    const int KT_ = KDIM / 16;

    auto prefetch = [&](int kt, int buf) {
        const float* Ag = A + (size_t)m0 * KDIM + kt * 16;
        const float* Bg = Wt + (size_t)n0 * KDIM + kt * 16;
        uint32_t abase = sbase + (uint32_t)(buf * 2 * TILESZ) * 4;
        uint32_t bbase = abase + (uint32_t)TILESZ * 4;
#pragma unroll
        for (int p = 0; p < 2; p++) {
            int r = sr + p * 64;
            uint32_t so = (uint32_t)(r * TSTRIDE + scq * 4) * 4;
            cp_async16(abase + so, Ag + (size_t)r * KDIM + scq * 4);
            cp_async16(bbase + so, Bg + (size_t)r * KDIM + scq * 4);
        }
        cp_commit();
    };

    prefetch(0, 0);

    for (int kt = 0; kt < KT_; kt++) {
        int buf = kt & 1;
        if (kt + 1 < KT_) {
            prefetch(kt + 1, buf ^ 1);
            cp_wait<1>();
        } else {
            cp_wait<0>();
        }
        __syncthreads();

        uint32_t abase = sbase + (uint32_t)(buf * 2 * TILESZ) * 4 + aoff;
        uint32_t bbase = sbase + (uint32_t)(buf * 2 * TILESZ + TILESZ) * 4 + boff;

#pragma unroll
        for (int ks = 0; ks < 2; ks++) {
            const uint32_t kbb = ks * 8 * 4;  // byte offset of k-halfstep
            uint32_t afr[4][4];
#pragma unroll
            for (int i = 0; i < 4; i++)
                ldsm4(afr[i][0], afr[i][1], afr[i][2], afr[i][3],
                      abase + kbb + (uint32_t)(i * 16 * TSTRIDE) * 4);
            uint32_t bfr[2][4];
#pragma unroll
            for (int j2 = 0; j2 < 2; j2++)
                ldsm4(bfr[j2][0], bfr[j2][1], bfr[j2][2], bfr[j2][3],
                      bbase + kbb + (uint32_t)(j2 * 16 * TSTRIDE) * 4);
#pragma unroll
            for (int i = 0; i < 4; i++)
#pragma unroll
                for (int j = 0; j < 4; j++)
                    mma_tf32(acc[i][j], afr[i], &bfr[j >> 1][(j & 1) * 2]);
        }
        __syncthreads();
    }

    // epilogue: bias + exact gelu + HAT gate (+ residual for MODE 2)
#pragma unroll
    for (int j = 0; j < 4; j++) {
        int col = n0 + warp_n * 32 + j * 8 + 2 * tg;
        float2 bb = *(const float2*)&bias[col];
        float2 gg = *(const float2*)&gate[col];
#pragma unroll
        for (int i = 0; i < 4; i++) {
            int row = m0 + warp_m * 64 + i * 16 + g;
            float v00 = gelu_exact(acc[i][j].x + bb.x) * gg.x;
            float v01 = gelu_exact(acc[i][j].y + bb.y) * gg.y;
            float v10 = gelu_exact(acc[i][j].z + bb.x) * gg.x;
            float v11 = gelu_exact(acc[i][j].w + bb.y) * gg.y;
            if (MODE == 2) {
                float2 x0 = *(const float2*)&xin[(size_t)row * NDIM + col];
                float2 x1 = *(const float2*)&xin[(size_t)(row + 8) * NDIM + col];
                v00 += x0.x; v01 += x0.y;
                v10 += x1.x; v11 += x1.y;
            }
            *(float2*)&C[(size_t)row * NDIM + col] = make_float2(v00, v01);
            *(float2*)&C[(size_t)(row + 8) * NDIM + col] = make_float2(v10, v11);
        }
    }
}

// ---------------------------------------------------------------------------
// Launch. Input order: x, t, s, fc1_w, fc1_b, fc2_w, fc2_b, efc1, efc2,
//                      sem_w, sem_b, route_w, larger_w, larger_b, elarger
// Pure kernel launches only — capture-safe.
// ---------------------------------------------------------------------------
extern "C" void kernel_launch(void* const* d_in, const int* in_sizes, int n_in,
                              void* d_out, int out_size) {
    const float* x       = (const float*)d_in[0];
    const int*   tptr    = (const int*)d_in[1];
    const int*   sptr    = (const int*)d_in[2];
    const float* fc1w    = (const float*)d_in[3];
    const float* fc1b    = (const float*)d_in[4];
    const float* fc2w    = (const float*)d_in[5];
    const float* fc2b    = (const float*)d_in[6];
    const float* efc1    = (const float*)d_in[7];
    const float* efc2    = (const float*)d_in[8];
    const float* semw    = (const float*)d_in[9];
    const float* semb    = (const float*)d_in[10];
    const float* routew  = (const float*)d_in[11];
    const float* largerw = (const float*)d_in[12];
    const float* largerb = (const float*)d_in[13];
    const float* elarger = (const float*)d_in[14];
    float* out = (float*)d_out;

    k0_gates<<<1, 768>>>(efc1, efc2, elarger, tptr, sptr);
    kT<1><<<dim3(HDIM / 32, ADIM / 32), dim3(32, 8)>>>(fc1w, HDIM, ADIM);
    kT<2><<<dim3(ADIM / 32, HDIM / 32), dim3(32, 8)>>>(fc2w, ADIM, HDIM);
    k1_sem<<<MROWS / 128, 128>>>(x, semw, semb);
    k2_route<<<MROWS / 256, 256>>>(routew, tptr);
    k3_h2<<<MROWS / 32, 256>>>(x, largerw, largerb);
    gemm_mma<HDIM, ADIM, 1><<<dim3(ADIM / 128, MROWS / 128), 256, GEMM_SMEM_BYTES>>>(
        fc1b, nullptr, nullptr);
    gemm_mma<ADIM, HDIM, 2><<<dim3(HDIM / 128, MROWS / 128), 256, GEMM_SMEM_BYTES>>>(
        fc2b, x, out);
}

// round 6
// speedup vs baseline: 1.6866x; 1.6866x over previous
#include <cuda_runtime.h>
#include <cuda_bf16.h>
#include <math.h>
#include <stdint.h>

// ---------------------------------------------------------------------------
// BertAdapterCapsuleMask fused pipeline — Round 6.
//  * k12: fused semantic GEMM (tf32 mma) + squash + dynamic routing
//  * adapter GEMMs: bf16 m16n8k16 mma, BK=32 double-buffered cp.async
//  * h2 / a / transposed weights stored bf16
// Shapes: B=256 S=128 H=768 A=512 N=10 C=3 K=3.  M = 32768.
// ---------------------------------------------------------------------------

#define MROWS 32768
#define HDIM  768
#define ADIM  512

// Scratch (static device globals; no allocations anywhere)
__device__ __nv_bfloat16 g_h2[(size_t)MROWS * HDIM];
__device__ __nv_bfloat16 g_a[(size_t)MROWS * ADIM];
__device__ __nv_bfloat16 g_wt1[(size_t)ADIM * HDIM];   // fc1_w^T bf16 [512][768]
__device__ __nv_bfloat16 g_wt2[(size_t)HDIM * ADIM];   // fc2_w^T bf16 [768][512]
__device__ float g_semwt[32 * HDIM];                   // semW^T f32 [32][768] (rows 30,31 zero)
__device__ float g_vote[(size_t)3 * MROWS * 3];        // (K,M,C)
__device__ float g_gfc1[ADIM];
__device__ float g_gfc2[HDIM];
__device__ float g_glarger[HDIM];

__device__ __forceinline__ float gelu_exact(float v) {
    return 0.5f * v * (1.0f + erff(v * 0.7071067811865476f));
}
__device__ __forceinline__ float sigmoid_(float z) {
    return 1.0f / (1.0f + expf(-z));
}

// ---- cp.async helpers
__device__ __forceinline__ void cp_async16(uint32_t smem_dst, const void* gsrc) {
    asm volatile("cp.async.cg.shared.global [%0], [%1], 16;" ::"r"(smem_dst), "l"(gsrc));
}
__device__ __forceinline__ void cp_commit() {
    asm volatile("cp.async.commit_group;");
}
template <int N>
__device__ __forceinline__ void cp_wait() {
    asm volatile("cp.async.wait_group %0;" ::"n"(N));
}

// ---- ldmatrix x4 (b16 tiles)
__device__ __forceinline__ void ldsm4(uint32_t& r0, uint32_t& r1, uint32_t& r2,
                                      uint32_t& r3, uint32_t addr) {
    asm volatile("ldmatrix.sync.aligned.m8n8.x4.shared.b16 {%0,%1,%2,%3}, [%4];"
                 : "=r"(r0), "=r"(r1), "=r"(r2), "=r"(r3)
                 : "r"(addr));
}

// ---- mma variants
__device__ __forceinline__ void mma_tf32(float4& d, const uint32_t* a, const uint32_t* b) {
    asm volatile(
        "mma.sync.aligned.m16n8k8.row.col.f32.tf32.tf32.f32 "
        "{%0,%1,%2,%3}, {%4,%5,%6,%7}, {%8,%9}, {%0,%1,%2,%3};"
        : "+f"(d.x), "+f"(d.y), "+f"(d.z), "+f"(d.w)
        : "r"(a[0]), "r"(a[1]), "r"(a[2]), "r"(a[3]), "r"(b[0]), "r"(b[1]));
}
__device__ __forceinline__ void mma_bf16(float4& d, const uint32_t* a, const uint32_t* b) {
    asm volatile(
        "mma.sync.aligned.m16n8k16.row.col.f32.bf16.bf16.f32 "
        "{%0,%1,%2,%3}, {%4,%5,%6,%7}, {%8,%9}, {%0,%1,%2,%3};"
        : "+f"(d.x), "+f"(d.y), "+f"(d.z), "+f"(d.w)
        : "r"(a[0]), "r"(a[1]), "r"(a[2]), "r"(a[3]), "r"(b[0]), "r"(b[1]));
}

// ---------------------------------------------------------------------------
// K0: HAT gates.  g = sigmoid(s * e[t])
// ---------------------------------------------------------------------------
__global__ void k0_gates(const float* __restrict__ efc1, const float* __restrict__ efc2,
                         const float* __restrict__ elarger,
                         const int* __restrict__ tp, const int* __restrict__ sp) {
    int t = *tp;
    float s = (float)(*sp);
    int h = threadIdx.x;  // 768 threads
    g_glarger[h] = sigmoid_(s * elarger[t * HDIM + h]);
    g_gfc2[h]    = sigmoid_(s * efc2[t * HDIM + h]);
    if (h < ADIM) g_gfc1[h] = sigmoid_(s * efc1[t * ADIM + h]);
}

// ---------------------------------------------------------------------------
// KT: weight transpose + bf16 convert.  W[K][N] -> Wt[N][K] bf16.
// ---------------------------------------------------------------------------
template <int WHICH>
__global__ void kT(const float* __restrict__ W, int K, int N) {
    __nv_bfloat16* Wt = (WHICH == 1) ? g_wt1 : g_wt2;
    __shared__ float t[32][33];
    int k0 = blockIdx.x * 32, n0 = blockIdx.y * 32;
    int tx = threadIdx.x, ty = threadIdx.y;  // block (32, 8)
#pragma unroll
    for (int p = 0; p < 32; p += 8) t[ty + p][tx] = W[(size_t)(k0 + ty + p) * N + n0 + tx];
    __syncthreads();
#pragma unroll
    for (int p = 0; p < 32; p += 8)
        Wt[(size_t)(n0 + ty + p) * K + k0 + tx] = __float2bfloat16(t[tx][ty + p]);
}

// ---------------------------------------------------------------------------
// KTsem: semW (N,H,C) -> g_semwt[o][k], o = c*10+n, rows 30..31 zeroed (f32).
// ---------------------------------------------------------------------------
__global__ void kTsem(const float* __restrict__ semw) {
    int idx = blockIdx.x * 256 + threadIdx.x;  // 96 blocks * 256 = 24576 = 32*768
    int o = idx / HDIM, k = idx % HDIM;
    float v = 0.0f;
    if (o < 30) {
        int c = o / 10, n = o % 10;
        v = semw[(size_t)n * HDIM * 3 + k * 3 + c];
    }
    g_semwt[o * HDIM + k] = v;
}

// ---------------------------------------------------------------------------
// K12: fused semantic-capsule GEMM (tf32 mma, BM=128 BN=32 BK=16) + squash +
// dynamic routing.  C tile handed to routing via smem; writes g_vote only.
// 256 threads = 8 warps along M (16 rows each), 4 n8-tiles wide.
// ---------------------------------------------------------------------------
#define TS12 20                    // f32 pitch (80B, ldmatrix conflict-free)
#define A12  (128 * TS12)          // 2560 floats per A stage
#define B12  (32 * TS12)           // 640 floats per B stage

__global__ __launch_bounds__(256) void k12_semroute(const float* __restrict__ x,
                                                    const float* __restrict__ semb,
                                                    const float* __restrict__ routew,
                                                    const int* __restrict__ tp) {
    __shared__ float As[2 * A12];
    __shared__ float Bs[2 * B12];
    __shared__ float Cs[128 * 33];
    __shared__ float rw[272];
    __shared__ float bs[32];

    const int tid = threadIdx.x;
    const int lane = tid & 31;
    const int warp_m = tid >> 5;                 // 0..7, rows warp_m*16
    const int m0 = blockIdx.x * 128;

    if (tid < 270) rw[tid] = routew[tid];
    if (tid < 32) {
        float b = 0.0f;
        if (tid < 30) { int c = tid / 10, n = tid % 10; b = semb[n * 3 + c]; }
        bs[tid] = b;
    }

    // staging maps
    const int sr = tid >> 2;       // A: rows sr, sr+64
    const int scq = tid & 3;
    const int brow = tid >> 2;     // B: tid<128 -> rows 0..31
    uint32_t sA = (uint32_t)__cvta_generic_to_shared(As);
    uint32_t sB = (uint32_t)__cvta_generic_to_shared(Bs);

    // ldmatrix lane addresses (byte offsets in tile)
    const uint32_t aoff = (uint32_t)((warp_m * 16 + (lane & 15)) * TS12 + (lane >> 4) * 4) * 4;
    const int b_row = (lane & 7) + ((lane >> 4) << 3);
    const int b_k4 = ((lane >> 3) & 1) * 4;

    float4 acc[4];
#pragma unroll
    for (int j = 0; j < 4; j++) acc[j] = make_float4(0.f, 0.f, 0.f, 0.f);

    auto prefetch = [&](int kt, int buf) {
        const float* Ag = x + (size_t)m0 * HDIM + kt * 16;
        const float* Bg = g_semwt + kt * 16;
        uint32_t ab = sA + (uint32_t)(buf * A12) * 4;
        uint32_t bb = sB + (uint32_t)(buf * B12) * 4;
#pragma unroll
        for (int p = 0; p < 2; p++) {
            int r = sr + p * 64;
            cp_async16(ab + (uint32_t)(r * TS12 + scq * 4) * 4,
                       Ag + (size_t)r * HDIM + scq * 4);
        }
        if (tid < 128)
            cp_async16(bb + (uint32_t)(brow * TS12 + scq * 4) * 4,
                       Bg + (size_t)brow * HDIM + scq * 4);
        cp_commit();
    };

    prefetch(0, 0);
    const int KT_ = HDIM / 16;  // 48
    for (int kt = 0; kt < KT_; kt++) {
        int buf = kt & 1;
        if (kt + 1 < KT_) { prefetch(kt + 1, buf ^ 1); cp_wait<1>(); }
        else { cp_wait<0>(); }
        __syncthreads();

        uint32_t ab = sA + (uint32_t)(buf * A12) * 4 + aoff;
        uint32_t bb = sB + (uint32_t)(buf * B12) * 4;
#pragma unroll
        for (int ks = 0; ks < 2; ks++) {
            const uint32_t kbb = ks * 8 * 4;
            uint32_t afr[4];
            ldsm4(afr[0], afr[1], afr[2], afr[3], ab + kbb);
            uint32_t bfr[2][4];
#pragma unroll
            for (int j2 = 0; j2 < 2; j2++)
                ldsm4(bfr[j2][0], bfr[j2][1], bfr[j2][2], bfr[j2][3],
                      bb + kbb + (uint32_t)((b_row + j2 * 16) * TS12 + b_k4) * 4);
#pragma unroll
            for (int j = 0; j < 4; j++)
                mma_tf32(acc[j], afr, &bfr[j >> 1][(j & 1) * 2]);
        }
        __syncthreads();
    }

    // C -> smem with bias
    {
        int r = warp_m * 16 + (lane >> 2);
        int cc = 2 * (lane & 3);
#pragma unroll
        for (int j = 0; j < 4; j++) {
            int col = j * 8 + cc;
            Cs[r * 33 + col]           = acc[j].x + bs[col];
            Cs[r * 33 + col + 1]       = acc[j].y + bs[col + 1];
            Cs[(r + 8) * 33 + col]     = acc[j].z + bs[col];
            Cs[(r + 8) * 33 + col + 1] = acc[j].w + bs[col + 1];
        }
    }
    __syncthreads();

    // routing epilogue: one thread per row (tid < 128)
    if (tid < 128) {
        int t = *tp;
        int m = m0 + tid;
        float v[30];
#pragma unroll
        for (int i = 0; i < 30; i++) v[i] = Cs[tid * 33 + i];

        // squash over n for each c
#pragma unroll
        for (int c = 0; c < 3; c++) {
            float sn = 1e-16f;
#pragma unroll
            for (int n = 0; n < 10; n++) { float q = v[c * 10 + n]; sn += q * q; }
            float sc = sqrtf(sn) / (1.0f + sn);
#pragma unroll
            for (int n = 0; n < 10; n++) v[c * 10 + n] *= sc;
        }

#pragma unroll
        for (int k = 0; k < 3; k++) {
            float pr[10][3];
#pragma unroll
            for (int n = 0; n < 10; n++) {
                float u0 = v[n * 3 + 0], u1 = v[n * 3 + 1], u2 = v[n * 3 + 2];
#pragma unroll
                for (int d = 0; d < 3; d++) {
                    int b = ((k * 10 + n) * 3) * 3 + d;
                    pr[n][d] = u0 * rw[b] + u1 * rw[b + 3] + u2 * rw[b + 6];
                }
            }
            float lg[10];
#pragma unroll
            for (int n = 0; n < 10; n++) lg[n] = 0.0f;
            float vote0 = 0.f, vote1 = 0.f, vote2 = 0.f;
#pragma unroll
            for (int it = 0; it < 3; it++) {
                float mx = -3.4e38f;
#pragma unroll
                for (int n = 0; n < 10; n++) {
                    lg[n] = (n <= t) ? lg[n] : -10000.0f;
                    mx = fmaxf(mx, lg[n]);
                }
                float e[10], ssum = 0.f;
#pragma unroll
                for (int n = 0; n < 10; n++) { e[n] = expf(lg[n] - mx); ssum += e[n]; }
                float inv = 1.0f / ssum;
                vote0 = vote1 = vote2 = 0.f;
#pragma unroll
                for (int n = 0; n < 10; n++) {
                    float p = e[n] * inv;
                    vote0 += p * pr[n][0];
                    vote1 += p * pr[n][1];
                    vote2 += p * pr[n][2];
                }
                if (it < 2) {
                    float sn = vote0 * vote0 + vote1 * vote1 + vote2 * vote2 + 1e-16f;
                    float sc = sqrtf(sn) / (1.0f + sn);
                    float o0 = vote0 * sc, o1 = vote1 * sc, o2 = vote2 * sc;
#pragma unroll
                    for (int n = 0; n < 10; n++)
                        lg[n] += pr[n][0] * o0 + pr[n][1] * o1 + pr[n][2] * o2;
                }
            }
            size_t base = ((size_t)k * MROWS + m) * 3;
            g_vote[base + 0] = vote0;
            g_vote[base + 1] = vote1;
            g_vote[base + 2] = vote2;
        }
    }
}

// ---------------------------------------------------------------------------
// K3: h2 = x + glarger * (vote9 @ larger_w + larger_b), bf16 output.
// ---------------------------------------------------------------------------
__global__ __launch_bounds__(256) void k3_h2(const float* __restrict__ x,
                                             const float* __restrict__ lw,
                                             const float* __restrict__ lb) {
    __shared__ float v9s[32 * 9];
    int m0 = blockIdx.x * 32;
    int tid = threadIdx.x;
    for (int i = tid; i < 288; i += 256) v9s[i] = g_vote[(size_t)m0 * 9 + i];
    __syncthreads();

#pragma unroll
    for (int p = 0; p < 3; p++) {
        int h = tid + p * 256;
        float lwr[9];
#pragma unroll
        for (int j = 0; j < 9; j++) lwr[j] = lw[j * HDIM + h];
        float gl = g_glarger[h];
        float bb = lb[h];
#pragma unroll 4
        for (int r = 0; r < 32; r++) {
            float acc = bb;
#pragma unroll
            for (int j = 0; j < 9; j++) acc += lwr[j] * v9s[r * 9 + j];
            size_t idx = (size_t)(m0 + r) * HDIM + h;
            g_h2[idx] = __float2bfloat16(x[idx] + gl * acc);
        }
    }
}

// ---------------------------------------------------------------------------
// Adapter GEMMs: bf16 m16n8k16 mma, ldmatrix fragments.
// BM=128 BN=128 BK=32, 256 threads = 8 warps (2 M x 4 N), warp tile 64x32.
// Tiles: [128][40] bf16, pitch 80B (16B-aligned rows, conflict-free ldmatrix).
// 2-stage cp.async double buffering; static smem 40 KB.
// MODE 1: a(bf16) = gelu(h2 @ fc1_w + b) * gfc1
// MODE 2: out(f32) = x + gelu(a @ fc2_w + b) * gfc2
// ---------------------------------------------------------------------------
#define BPITCH 40                      // bf16 elements per row (80 bytes)
#define BTILE  (128 * BPITCH)          // elements per stage per operand

template <int KDIM, int NDIM, int MODE>
__global__ __launch_bounds__(256, 2) void gemm_bf16(const float* __restrict__ bias,
                                                    const float* __restrict__ xin,
                                                    float* __restrict__ outp) {
    __shared__ __nv_bfloat16 As[2 * BTILE];
    __shared__ __nv_bfloat16 Bs[2 * BTILE];

    const __nv_bfloat16* A  = (MODE == 1) ? g_h2 : g_a;
    const __nv_bfloat16* Wt = (MODE == 1) ? g_wt1 : g_wt2;
    const float* gate       = (MODE == 1) ? g_gfc1 : g_gfc2;

    const int tid = threadIdx.x;
    const int lane = tid & 31;
    const int wid = tid >> 5;
    const int warp_m = wid >> 2;   // 0..1
    const int warp_n = wid & 3;    // 0..3
    const int g = lane >> 2;       // 0..7
    const int tg = lane & 3;       // 0..3

    const int n0 = blockIdx.x * 128;
    const int m0 = blockIdx.y * 128;

    // staging: tile 128 rows x 32 bf16 (64B) = 512 x 16B chunks, 2/thread
    const int sr = tid >> 2;       // rows sr, sr+64
    const int scq = tid & 3;       // 16B chunk within row

    uint32_t sA = (uint32_t)__cvta_generic_to_shared(As);
    uint32_t sB = (uint32_t)__cvta_generic_to_shared(Bs);

    // ldmatrix lane addresses (byte offsets within tile)
    const uint32_t aoff =
        (uint32_t)(warp_m * 64 + (lane & 15)) * 80 + (uint32_t)(lane >> 4) * 16;
    const uint32_t boff =
        (uint32_t)(warp_n * 32 + (lane & 7) + ((lane >> 4) << 3)) * 80 +
        (uint32_t)((lane >> 3) & 1) * 16;

    float4 acc[4][4];
#pragma unroll
    for (int i = 0; i < 4; i++)
#pragma unroll
        for (int j = 0; j < 4; j++) acc[i][j] = make_float4(0.f, 0.f, 0.f, 0.f);

    const int KT_ = KDIM / 32;

    auto prefetch = [&](int kt, int buf) {
        const __nv_bfloat16* Ag = A + (size_t)m0 * KDIM + kt * 32;
        const __nv_bfloat16* Bg = Wt + (size_t)n0 * KDIM + kt * 32;
        uint32_t ab = sA + (uint32_t)(buf * BTILE) * 2;
        uint32_t bb = sB + (uint32_t)(buf * BTILE) * 2;
#pragma unroll
        for (int p = 0; p < 2; p++) {
            int r = sr + p * 64;
            uint32_t so = (uint32_t)r * 80 + (uint32_t)scq * 16;
            cp_async16(ab + so, Ag + (size_t)r * KDIM + scq * 8);
            cp_async16(bb + so, Bg + (size_t)r * KDIM + scq * 8);
        }
        cp_commit();
    };

    prefetch(0, 0);

    for (int kt = 0; kt < KT_; kt++) {
        int buf = kt & 1;
        if (kt + 1 < KT_) { prefetch(kt + 1, buf ^ 1); cp_wait<1>(); }
        else { cp_wait<0>(); }
        __syncthreads();

        uint32_t ab = sA + (uint32_t)(buf * BTILE) * 2 + aoff;
        uint32_t bb = sB + (uint32_t)(buf * BTILE) * 2 + boff;

#pragma unroll
        for (int ks = 0; ks < 2; ks++) {           // two k16 steps per BK=32
            const uint32_t kbb = ks * 32;          // 16 bf16 = 32 bytes
            uint32_t afr[4][4];
#pragma unroll
            for (int i = 0; i < 4; i++)
                ldsm4(afr[i][0], afr[i][1], afr[i][2], afr[i][3],
                      ab + kbb + (uint32_t)(i * 16 * 80));
            uint32_t bfr[2][4];
#pragma unroll
            for (int j2 = 0; j2 < 2; j2++)
                ldsm4(bfr[j2][0], bfr[j2][1], bfr[j2][2], bfr[j2][3],
                      bb + kbb + (uint32_t)(j2 * 16 * 80));
#pragma unroll
            for (int i = 0; i < 4; i++)
#pragma unroll
                for (int j = 0; j < 4; j++)
                    mma_bf16(acc[i][j], afr[i], &bfr[j >> 1][(j & 1) * 2]);
        }
        __syncthreads();
    }

    // epilogue
#pragma unroll
    for (int j = 0; j < 4; j++) {
        int col = n0 + warp_n * 32 + j * 8 + 2 * tg;
        float2 bb = *(const float2*)&bias[col];
        float2 gg = *(const float2*)&gate[col];
#pragma unroll
        for (int i = 0; i < 4; i++) {
            int row = m0 + warp_m * 64 + i * 16 + g;
            float v00 = gelu_exact(acc[i][j].x + bb.x) * gg.x;
            float v01 = gelu_exact(acc[i][j].y + bb.y) * gg.y;
            float v10 = gelu_exact(acc[i][j].z + bb.x) * gg.x;
            float v11 = gelu_exact(acc[i][j].w + bb.y) * gg.y;
            if (MODE == 1) {
                __nv_bfloat162* dst0 = (__nv_bfloat162*)&g_a[(size_t)row * NDIM + col];
                __nv_bfloat162* dst1 = (__nv_bfloat162*)&g_a[(size_t)(row + 8) * NDIM + col];
                *dst0 = __floats2bfloat162_rn(v00, v01);
                *dst1 = __floats2bfloat162_rn(v10, v11);
            } else {
                float2 x0 = *(const float2*)&xin[(size_t)row * NDIM + col];
                float2 x1 = *(const float2*)&xin[(size_t)(row + 8) * NDIM + col];
                *(float2*)&outp[(size_t)row * NDIM + col] =
                    make_float2(v00 + x0.x, v01 + x0.y);
                *(float2*)&outp[(size_t)(row + 8) * NDIM + col] =
                    make_float2(v10 + x1.x, v11 + x1.y);
            }
        }
    }
}

// ---------------------------------------------------------------------------
// Launch. Input order: x, t, s, fc1_w, fc1_b, fc2_w, fc2_b, efc1, efc2,
//                      sem_w, sem_b, route_w, larger_w, larger_b, elarger
// Pure kernel launches only — capture-safe.
// ---------------------------------------------------------------------------
extern "C" void kernel_launch(void* const* d_in, const int* in_sizes, int n_in,
                              void* d_out, int out_size) {
    const float* x       = (const float*)d_in[0];
    const int*   tptr    = (const int*)d_in[1];
    const int*   sptr    = (const int*)d_in[2];
    const float* fc1w    = (const float*)d_in[3];
    const float* fc1b    = (const float*)d_in[4];
    const float* fc2w    = (const float*)d_in[5];
    const float* fc2b    = (const float*)d_in[6];
    const float* efc1    = (const float*)d_in[7];
    const float* efc2    = (const float*)d_in[8];
    const float* semw    = (const float*)d_in[9];
    const float* semb    = (const float*)d_in[10];
    const float* routew  = (const float*)d_in[11];
    const float* largerw = (const float*)d_in[12];
    const float* largerb = (const float*)d_in[13];
    const float* elarger = (const float*)d_in[14];
    float* out = (float*)d_out;

    k0_gates<<<1, 768>>>(efc1, efc2, elarger, tptr, sptr);
    kT<1><<<dim3(HDIM / 32, ADIM / 32), dim3(32, 8)>>>(fc1w, HDIM, ADIM);
    kT<2><<<dim3(ADIM / 32, HDIM / 32), dim3(32, 8)>>>(fc2w, ADIM, HDIM);
    kTsem<<<96, 256>>>(semw);
    k12_semroute<<<MROWS / 128, 256>>>(x, semb, routew, tptr);
    k3_h2<<<MROWS / 32, 256>>>(x, largerw, largerb);
    gemm_bf16<HDIM, ADIM, 1><<<dim3(ADIM / 128, MROWS / 128), 256>>>(fc1b, nullptr, nullptr);
    gemm_bf16<ADIM, HDIM, 2><<<dim3(HDIM / 128, MROWS / 128), 256>>>(fc2b, x, out);
}